// round 2
// baseline (speedup 1.0000x reference)
#include <cuda_runtime.h>

#define B_ 256
#define S_ 196
#define R_ 1024
#define H_ 512

// Scratch (no allocations allowed in kernel_launch)
__device__ float g_att_h[B_ * H_];
__device__ float g_scores[B_ * S_];

__device__ __forceinline__ float tanh_fast(float x) {
    float y;
    asm("tanh.approx.f32 %0, %1;" : "=f"(y) : "f"(x));
    return y;
}

// ---------------------------------------------------------------------------
// Kernel A: att_h[b,h] = sum_k hidden[b,k] * W[h,k] + bias[h]
// NT GEMM 256x512x1024, tiled 32x32x32, 256 threads, 2x2 micro-tile.
// ---------------------------------------------------------------------------
__global__ void k_h2att(const float* __restrict__ hidden,
                        const float* __restrict__ W,
                        const float* __restrict__ bias) {
    __shared__ float As[32][33];
    __shared__ float Bs[32][33];
    const int b0 = blockIdx.y * 32;
    const int h0 = blockIdx.x * 32;
    const int tid = threadIdx.x;          // 0..255
    const int tx = tid & 15;              // h micro
    const int ty = tid >> 4;              // b micro
    float acc00 = 0.f, acc01 = 0.f, acc10 = 0.f, acc11 = 0.f;

    for (int k0 = 0; k0 < R_; k0 += 32) {
        #pragma unroll
        for (int i = 0; i < 4; i++) {
            int idx = tid + i * 256;
            int r = idx >> 5, c = idx & 31;
            As[r][c] = hidden[(size_t)(b0 + r) * R_ + k0 + c];
            Bs[r][c] = W[(size_t)(h0 + r) * R_ + k0 + c];
        }
        __syncthreads();
        #pragma unroll
        for (int kk = 0; kk < 32; kk++) {
            float a0 = As[ty][kk],      a1 = As[ty + 16][kk];
            float w0 = Bs[tx][kk],      w1 = Bs[tx + 16][kk];
            acc00 = fmaf(a0, w0, acc00);
            acc01 = fmaf(a0, w1, acc01);
            acc10 = fmaf(a1, w0, acc10);
            acc11 = fmaf(a1, w1, acc11);
        }
        __syncthreads();
    }
    g_att_h[(size_t)(b0 + ty)      * H_ + h0 + tx]      = acc00 + bias[h0 + tx];
    g_att_h[(size_t)(b0 + ty)      * H_ + h0 + tx + 16] = acc01 + bias[h0 + tx + 16];
    g_att_h[(size_t)(b0 + ty + 16) * H_ + h0 + tx]      = acc10 + bias[h0 + tx];
    g_att_h[(size_t)(b0 + ty + 16) * H_ + h0 + tx + 16] = acc11 + bias[h0 + tx + 16];
}

// ---------------------------------------------------------------------------
// Kernel B: scores[b,s] = sum_h tanh(iw[b,s]*p[b,s,h] + att_h[b,h]) * alpha[h] + ab
// grid (49, 256), 128 threads (4 warps), warp per s, float4 coalesced loads.
// ---------------------------------------------------------------------------
__global__ void k_scores(const float* __restrict__ p_att,
                         const float* __restrict__ in_w,
                         const float* __restrict__ alpha_w,
                         const float* __restrict__ alpha_b) {
    __shared__ __align__(16) float sh_ah[H_];
    __shared__ __align__(16) float sh_al[H_];
    const int b = blockIdx.y;
    const int tid = threadIdx.x;

    for (int i = tid; i < H_; i += 128) {
        sh_ah[i] = g_att_h[(size_t)b * H_ + i];
        sh_al[i] = alpha_w[i];
    }
    __syncthreads();

    const int warp = tid >> 5, lane = tid & 31;
    const int s = blockIdx.x * 4 + warp;
    if (s < S_) {
        const float iw = in_w[b * S_ + s];
        const float4* p4  = (const float4*)(p_att + ((size_t)b * S_ + s) * H_);
        const float4* ah4 = (const float4*)sh_ah;
        const float4* al4 = (const float4*)sh_al;
        float acc = 0.f;
        #pragma unroll
        for (int j = 0; j < 4; j++) {
            float4 p = p4[j * 32 + lane];
            float4 a = ah4[j * 32 + lane];
            float4 w = al4[j * 32 + lane];
            acc += tanh_fast(fmaf(iw, p.x, a.x)) * w.x;
            acc += tanh_fast(fmaf(iw, p.y, a.y)) * w.y;
            acc += tanh_fast(fmaf(iw, p.z, a.z)) * w.z;
            acc += tanh_fast(fmaf(iw, p.w, a.w)) * w.w;
        }
        #pragma unroll
        for (int o = 16; o; o >>= 1)
            acc += __shfl_xor_sync(0xffffffffu, acc, o);
        if (lane == 0)
            g_scores[b * S_ + s] = acc + alpha_b[0];
    }
}

// ---------------------------------------------------------------------------
// Kernel C: softmax over S per batch. One block per b, 256 threads.
// Writes weight into d_out's second region.
// ---------------------------------------------------------------------------
__global__ void k_softmax(float* __restrict__ weight_out) {
    __shared__ float red[8];
    const int b = blockIdx.x, tid = threadIdx.x;
    const int warp = tid >> 5, lane = tid & 31;

    float v = (tid < S_) ? g_scores[b * S_ + tid] : -1e30f;

    // block max
    float m = v;
    #pragma unroll
    for (int o = 16; o; o >>= 1) m = fmaxf(m, __shfl_xor_sync(0xffffffffu, m, o));
    if (lane == 0) red[warp] = m;
    __syncthreads();
    if (tid == 0) {
        float mm = red[0];
        #pragma unroll
        for (int i = 1; i < 8; i++) mm = fmaxf(mm, red[i]);
        red[0] = mm;
    }
    __syncthreads();
    m = red[0];
    __syncthreads();

    float e = (tid < S_) ? __expf(v - m) : 0.f;

    // block sum
    float su = e;
    #pragma unroll
    for (int o = 16; o; o >>= 1) su += __shfl_xor_sync(0xffffffffu, su, o);
    if (lane == 0) red[warp] = su;
    __syncthreads();
    if (tid == 0) {
        float ss = 0.f;
        #pragma unroll
        for (int i = 0; i < 8; i++) ss += red[i];
        red[0] = ss;
    }
    __syncthreads();
    float inv = 1.0f / red[0];

    if (tid < S_) weight_out[b * S_ + tid] = e * inv;
}

// ---------------------------------------------------------------------------
// Kernel D: att_res[b,r] = sum_s weight[b,s] * att_feats[b,s,r]
// grid (4, 256), 64 threads; each thread owns one float4 column slice.
// ---------------------------------------------------------------------------
__global__ void k_pool(const float* __restrict__ att_feats,
                       const float* __restrict__ weight,
                       float* __restrict__ out) {
    __shared__ float ws[S_];
    const int b = blockIdx.y;
    const int tid = threadIdx.x;  // 0..63
    for (int i = tid; i < S_; i += 64) ws[i] = weight[b * S_ + i];
    __syncthreads();

    const int r4 = blockIdx.x * 64 + tid;   // float4 index 0..255
    const float4* af = (const float4*)(att_feats + (size_t)b * S_ * R_);
    float4 acc = make_float4(0.f, 0.f, 0.f, 0.f);

    #pragma unroll 4
    for (int s = 0; s < S_; s++) {
        float w = ws[s];
        float4 v = af[(size_t)s * (R_ / 4) + r4];
        acc.x = fmaf(w, v.x, acc.x);
        acc.y = fmaf(w, v.y, acc.y);
        acc.z = fmaf(w, v.z, acc.z);
        acc.w = fmaf(w, v.w, acc.w);
    }
    ((float4*)(out + (size_t)b * R_))[r4] = acc;
}

// ---------------------------------------------------------------------------
extern "C" void kernel_launch(void* const* d_in, const int* in_sizes, int n_in,
                              void* d_out, int out_size) {
    const float* att_feats = (const float*)d_in[0];  // [B,S,R]
    const float* p_att     = (const float*)d_in[1];  // [B,S,H]
    const float* hidden    = (const float*)d_in[2];  // [B,R]
    const float* in_w      = (const float*)d_in[3];  // [B,S]
    const float* h2w       = (const float*)d_in[4];  // [H,R]
    const float* h2b       = (const float*)d_in[5];  // [H]
    const float* aw        = (const float*)d_in[6];  // [1,H]
    const float* ab        = (const float*)d_in[7];  // [1]

    float* out     = (float*)d_out;
    float* att_res = out;                 // [B,R] = 262144 floats
    float* weight  = out + B_ * R_;       // [B,S] =  50176 floats

    k_h2att  <<<dim3(H_ / 32, B_ / 32), 256>>>(hidden, h2w, h2b);
    k_scores <<<dim3((S_ + 3) / 4, B_), 128>>>(p_att, in_w, aw, ab);
    k_softmax<<<B_, 256>>>(weight);
    k_pool   <<<dim3(4, B_), 64>>>(att_feats, weight, att_res);
}

// round 3
// speedup vs baseline: 1.3315x; 1.3315x over previous
#include <cuda_runtime.h>

#define B_ 256
#define S_ 196
#define R_ 1024
#define H_ 512

#define KSPLIT 4          // k_h2att K-split
#define KCHUNK (R_ / KSPLIT)
#define NSPOOL 4          // k_pool S-split
#define SCHUNK (S_ / NSPOOL)   // 49

// Scratch (no allocations allowed anywhere)
__device__ float g_att_h_part[KSPLIT * B_ * H_];
__device__ float g_scores[B_ * S_];
__device__ float g_pool_part[NSPOOL * B_ * R_];

__device__ __forceinline__ float tanh_fast(float x) {
    float y;
    asm("tanh.approx.f32 %0, %1;" : "=f"(y) : "f"(x));
    return y;
}

// ---------------------------------------------------------------------------
// Kernel A: partial att_h. grid (H/32, B/32, KSPLIT), 256 threads.
// Each block: 32x32 output tile over a 256-wide K chunk. Bias added in split 0.
// ---------------------------------------------------------------------------
__global__ void k_h2att(const float* __restrict__ hidden,
                        const float* __restrict__ W,
                        const float* __restrict__ bias) {
    __shared__ float As[32][33];
    __shared__ float Bs[32][33];
    const int b0 = blockIdx.y * 32;
    const int h0 = blockIdx.x * 32;
    const int z  = blockIdx.z;
    const int tid = threadIdx.x;
    const int tx = tid & 15;
    const int ty = tid >> 4;
    float acc00 = 0.f, acc01 = 0.f, acc10 = 0.f, acc11 = 0.f;

    const int kbeg = z * KCHUNK;
    for (int k0 = kbeg; k0 < kbeg + KCHUNK; k0 += 32) {
        #pragma unroll
        for (int i = 0; i < 4; i++) {
            int idx = tid + i * 256;
            int r = idx >> 5, c = idx & 31;
            As[r][c] = hidden[(size_t)(b0 + r) * R_ + k0 + c];
            Bs[r][c] = W[(size_t)(h0 + r) * R_ + k0 + c];
        }
        __syncthreads();
        #pragma unroll
        for (int kk = 0; kk < 32; kk++) {
            float a0 = As[ty][kk],      a1 = As[ty + 16][kk];
            float w0 = Bs[tx][kk],      w1 = Bs[tx + 16][kk];
            acc00 = fmaf(a0, w0, acc00);
            acc01 = fmaf(a0, w1, acc01);
            acc10 = fmaf(a1, w0, acc10);
            acc11 = fmaf(a1, w1, acc11);
        }
        __syncthreads();
    }
    float b00 = 0.f, b16 = 0.f;
    if (z == 0) { b00 = bias[h0 + tx]; b16 = bias[h0 + tx + 16]; }
    float* outp = g_att_h_part + (size_t)z * B_ * H_;
    outp[(size_t)(b0 + ty)      * H_ + h0 + tx]      = acc00 + b00;
    outp[(size_t)(b0 + ty)      * H_ + h0 + tx + 16] = acc01 + b16;
    outp[(size_t)(b0 + ty + 16) * H_ + h0 + tx]      = acc10 + b00;
    outp[(size_t)(b0 + ty + 16) * H_ + h0 + tx + 16] = acc11 + b16;
}

// ---------------------------------------------------------------------------
// Kernel B: scores. grid (25, 256), 256 threads (8 warps = 8 s each).
// Folds the 4-way att_h partial reduction into the shared-memory load.
// ---------------------------------------------------------------------------
__global__ void k_scores(const float* __restrict__ p_att,
                         const float* __restrict__ in_w,
                         const float* __restrict__ alpha_w,
                         const float* __restrict__ alpha_b) {
    __shared__ __align__(16) float sh_ah[H_];
    __shared__ __align__(16) float sh_al[H_];
    const int b = blockIdx.y;
    const int tid = threadIdx.x;

    for (int i = tid; i < H_; i += 256) {
        size_t o = (size_t)b * H_ + i;
        float v = g_att_h_part[o]
                + g_att_h_part[(size_t)1 * B_ * H_ + o]
                + g_att_h_part[(size_t)2 * B_ * H_ + o]
                + g_att_h_part[(size_t)3 * B_ * H_ + o];
        sh_ah[i] = v;
        sh_al[i] = alpha_w[i];
    }
    __syncthreads();

    const int warp = tid >> 5, lane = tid & 31;
    const int s = blockIdx.x * 8 + warp;
    if (s < S_) {
        const float iw = in_w[b * S_ + s];
        const float4* p4  = (const float4*)(p_att + ((size_t)b * S_ + s) * H_);
        const float4* ah4 = (const float4*)sh_ah;
        const float4* al4 = (const float4*)sh_al;
        float acc = 0.f;
        #pragma unroll
        for (int j = 0; j < 4; j++) {
            float4 p = p4[j * 32 + lane];
            float4 a = ah4[j * 32 + lane];
            float4 w = al4[j * 32 + lane];
            acc += tanh_fast(fmaf(iw, p.x, a.x)) * w.x;
            acc += tanh_fast(fmaf(iw, p.y, a.y)) * w.y;
            acc += tanh_fast(fmaf(iw, p.z, a.z)) * w.z;
            acc += tanh_fast(fmaf(iw, p.w, a.w)) * w.w;
        }
        #pragma unroll
        for (int o = 16; o; o >>= 1)
            acc += __shfl_xor_sync(0xffffffffu, acc, o);
        if (lane == 0)
            g_scores[b * S_ + s] = acc + alpha_b[0];
    }
}

// ---------------------------------------------------------------------------
// Kernel C: softmax over S per batch. One block per b, 256 threads.
// ---------------------------------------------------------------------------
__global__ void k_softmax(float* __restrict__ weight_out) {
    __shared__ float red[8];
    const int b = blockIdx.x, tid = threadIdx.x;
    const int warp = tid >> 5, lane = tid & 31;

    float v = (tid < S_) ? g_scores[b * S_ + tid] : -1e30f;

    float m = v;
    #pragma unroll
    for (int o = 16; o; o >>= 1) m = fmaxf(m, __shfl_xor_sync(0xffffffffu, m, o));
    if (lane == 0) red[warp] = m;
    __syncthreads();
    if (tid == 0) {
        float mm = red[0];
        #pragma unroll
        for (int i = 1; i < 8; i++) mm = fmaxf(mm, red[i]);
        red[0] = mm;
    }
    __syncthreads();
    m = red[0];
    __syncthreads();

    float e = (tid < S_) ? __expf(v - m) : 0.f;

    float su = e;
    #pragma unroll
    for (int o = 16; o; o >>= 1) su += __shfl_xor_sync(0xffffffffu, su, o);
    if (lane == 0) red[warp] = su;
    __syncthreads();
    if (tid == 0) {
        float ss = 0.f;
        #pragma unroll
        for (int i = 0; i < 8; i++) ss += red[i];
        red[0] = ss;
    }
    __syncthreads();
    float inv = 1.0f / red[0];

    if (tid < S_) weight_out[b * S_ + tid] = e * inv;
}

// ---------------------------------------------------------------------------
// Kernel D1: partial pooling. grid (2, NSPOOL, 256), 128 threads.
// Each block: 128 float4 columns, 49 s values -> g_pool_part[sc][b][r].
// ---------------------------------------------------------------------------
__global__ void k_pool_part(const float* __restrict__ att_feats,
                            const float* __restrict__ weight) {
    __shared__ float ws[SCHUNK];
    const int b  = blockIdx.z;
    const int sc = blockIdx.y;
    const int tid = threadIdx.x;  // 0..127
    const int sbeg = sc * SCHUNK;

    if (tid < SCHUNK) ws[tid] = weight[b * S_ + sbeg + tid];
    __syncthreads();

    const int r4 = blockIdx.x * 128 + tid;   // float4 index 0..255
    const float4* af = (const float4*)(att_feats
                        + ((size_t)b * S_ + sbeg) * R_);
    float4 acc = make_float4(0.f, 0.f, 0.f, 0.f);

    #pragma unroll 7
    for (int s = 0; s < SCHUNK; s++) {
        float w = ws[s];
        float4 v = af[(size_t)s * (R_ / 4) + r4];
        acc.x = fmaf(w, v.x, acc.x);
        acc.y = fmaf(w, v.y, acc.y);
        acc.z = fmaf(w, v.z, acc.z);
        acc.w = fmaf(w, v.w, acc.w);
    }
    float4* part = (float4*)(g_pool_part + ((size_t)sc * B_ + b) * R_);
    part[r4] = acc;
}

// ---------------------------------------------------------------------------
// Kernel D2: reduce 4 partials -> att_res. 65536 float4 outputs.
// ---------------------------------------------------------------------------
__global__ void k_pool_reduce(float* __restrict__ out) {
    const int idx = blockIdx.x * 256 + threadIdx.x;   // float4 index over B*R/4
    const float4* p0 = (const float4*)g_pool_part;
    const float4* p1 = (const float4*)(g_pool_part + (size_t)1 * B_ * R_);
    const float4* p2 = (const float4*)(g_pool_part + (size_t)2 * B_ * R_);
    const float4* p3 = (const float4*)(g_pool_part + (size_t)3 * B_ * R_);
    float4 a = p0[idx], b = p1[idx], c = p2[idx], d = p3[idx];
    float4 r;
    r.x = (a.x + b.x) + (c.x + d.x);
    r.y = (a.y + b.y) + (c.y + d.y);
    r.z = (a.z + b.z) + (c.z + d.z);
    r.w = (a.w + b.w) + (c.w + d.w);
    ((float4*)out)[idx] = r;
}

// ---------------------------------------------------------------------------
extern "C" void kernel_launch(void* const* d_in, const int* in_sizes, int n_in,
                              void* d_out, int out_size) {
    const float* att_feats = (const float*)d_in[0];  // [B,S,R]
    const float* p_att     = (const float*)d_in[1];  // [B,S,H]
    const float* hidden    = (const float*)d_in[2];  // [B,R]
    const float* in_w      = (const float*)d_in[3];  // [B,S]
    const float* h2w       = (const float*)d_in[4];  // [H,R]
    const float* h2b       = (const float*)d_in[5];  // [H]
    const float* aw        = (const float*)d_in[6];  // [1,H]
    const float* ab        = (const float*)d_in[7];  // [1]

    float* out     = (float*)d_out;
    float* att_res = out;                 // [B,R]
    float* weight  = out + B_ * R_;       // [B,S]

    k_h2att      <<<dim3(H_ / 32, B_ / 32, KSPLIT), 256>>>(hidden, h2w, h2b);
    k_scores     <<<dim3((S_ + 7) / 8, B_), 256>>>(p_att, in_w, aw, ab);
    k_softmax    <<<B_, 256>>>(weight);
    k_pool_part  <<<dim3(2, NSPOOL, B_), 128>>>(att_feats, weight);
    k_pool_reduce<<<B_ * R_ / 4 / 256, 256>>>(att_res);
}